// round 11
// baseline (speedup 1.0000x reference)
#include <cuda_runtime.h>
#include <cstdint>

#define DINL __device__ __forceinline__
#define SCALE_F 0.022097086912079608f  // 1/sqrt(2048)

// ---------- scratch ----------
__device__ float g_J[640 * 2048];            // joint, tf32-rounded
__device__ float g_K[2 * 64 * 1024 * 16];    // keys, SCALE folded, tf32, d-rows PERMUTED
__device__ float g_V[2 * 640 * 1024];        // values, tf32, d-cols PERMUTED
__device__ float g_O[2 * 640 * 2048];        // relu(tanh(weighted)), tf32-rounded
__device__ float g_W[1310720];               // pre-rounded activations: [audio|video]

#define OW_A   0
#define OW_V   655360

DINL float tanhx(float x) {
    float y; asm("tanh.approx.f32 %0, %1;" : "=f"(y) : "f"(x)); return y;
}
DINL float f2tf(float x) {
    uint32_t r; asm("cvt.rna.tf32.f32 %0, %1;" : "=r"(r) : "f"(x));
    return __uint_as_float(r);
}
DINL void mma8(float* c, float a0, float a1, float a2, float a3, float b0, float b1) {
    asm volatile(
        "mma.sync.aligned.m16n8k8.row.col.f32.tf32.tf32.f32 "
        "{%0,%1,%2,%3},{%4,%5,%6,%7},{%8,%9},{%0,%1,%2,%3};"
        : "+f"(c[0]), "+f"(c[1]), "+f"(c[2]), "+f"(c[3])
        : "r"(__float_as_uint(a0)), "r"(__float_as_uint(a1)),
          "r"(__float_as_uint(a2)), "r"(__float_as_uint(a3)),
          "r"(__float_as_uint(b0)), "r"(__float_as_uint(b1)));
}
DINL int dperm(int c) {  // storage position of physical in-group index
    return (c & ~7) + 2 * (c & 3) + ((c & 7) >> 2);
}
DINL float* bufptr(int sel) {
    switch (sel) {
        case 0: return g_J;
        case 1: return g_V;
        default: return g_O;
    }
}
DINL void cpa16(uint32_t dst, const void* src) {
    asm volatile("cp.async.cg.shared.global [%0], [%1], 16;\n" :: "r"(dst), "l"(src));
}
DINL void cpa_commit() { asm volatile("cp.async.commit_group;\n" ::: "memory"); }
template<int W> DINL void cpa_wait() {
    asm volatile("cp.async.wait_group %0;\n" :: "n"(W) : "memory");
}

// ---------- pre-round activations only ----------
__global__ __launch_bounds__(256) void k_round_av(
    const float* __restrict__ a, const float* __restrict__ v)
{
    int i = blockIdx.x * 256 + threadIdx.x;     // float4 index, 327680 total
    const float4* src = (i < 163840) ? (const float4*)a : (const float4*)v;
    int base = (i < 163840) ? 0 : 163840;
    float4 x = src[i - base];
    x.x = f2tf(x.x); x.y = f2tf(x.y); x.z = f2tf(x.z); x.w = f2tf(x.w);
    ((float4*)g_W)[i] = x;
}

// ---------- key linears: permuted rows ----------
__global__ __launch_bounds__(256) void k_key(
    const float* __restrict__ audio, const float* __restrict__ video,
    const float* __restrict__ Wk1, const float* __restrict__ bk1,
    const float* __restrict__ Wk2, const float* __restrict__ bk2)
{
    int b = blockIdx.x, r = blockIdx.y;
    const float* X  = r ? video : audio;
    const float* Wk = r ? Wk2 : Wk1;
    const float* bk = r ? bk2 : bk1;
    __shared__ float sW[100], sb[10];
    if (threadIdx.x < 100) sW[threadIdx.x] = Wk[threadIdx.x];
    if (threadIdx.x < 10)  sb[threadIdx.x] = bk[threadIdx.x];
    __syncthreads();
    const float* xb = X + (size_t)b * 10240;
    float* kout = g_K + (size_t)(r * 64 + b) * 16384;
    for (int d = threadIdx.x; d < 1024; d += 256) {
        float a[10];
        #pragma unroll
        for (int t = 0; t < 10; ++t) a[t] = xb[t * 1024 + d];
        float* krow = kout + (size_t)dperm(d) * 16;
        #pragma unroll
        for (int t = 10; t < 16; ++t) krow[t] = 0.0f;
        #pragma unroll
        for (int t = 0; t < 10; ++t) {
            float s = sb[t];
            #pragma unroll
            for (int tp = 0; tp < 10; ++tp) s += a[tp] * sW[tp * 10 + t];
            krow[t] = f2tf(s * SCALE_F);
        }
    }
}

// ---------- tf32 GEMM: BM=64 BN=64 BK=32, 3-stage cp.async ----------
// A operands pre-rounded; B (weights) raw fp32, rounded in-loop after LDS.
// stage layout (floats): A[64*36]=2304 then B[32*68]=2176 -> 4480/stage, 3 stages
__global__ __launch_bounds__(256) void k_gemm_tc(
    const float* A0, const float* A1, const float* A0z, const float* A1z,
    int aSel, int Asplit, int lda,
    const float* W0, const float* W1, const float* bias0, const float* bias1,
    int cSel, size_t cStride, int M, int N, int K,
    int doRelu, int doRound, int doPerm)
{
    extern __shared__ float smg[];
    uint32_t sb32 = (uint32_t)__cvta_generic_to_shared(smg);
    int z = blockIdx.z;
    const float* Ap0, *Ap1;
    if (aSel < 0) { Ap0 = z ? A0z : A0; Ap1 = z ? A1z : A1; }
    else          { Ap0 = Ap1 = bufptr(aSel); }
    const float* W    = z ? W1 : W0;
    const float* bias = z ? bias1 : bias0;
    float* C = bufptr(cSel) + (size_t)z * cStride;

    int tid = threadIdx.x, lane = tid & 31, warp = tid >> 5;
    int g = lane >> 2, j = lane & 3;
    int wm = (warp >> 2) * 32, wn = (warp & 3) * 16;
    int row0 = blockIdx.y * 64, col0 = blockIdx.x * 64;
    float acc[2][2][4] = {};

    int nt = K >> 5;

    #define GEMM_ISSUE(TI, ST) do {                                             \
        int kb_ = (TI) << 5;                                                    \
        uint32_t sA_ = sb32 + (uint32_t)(ST) * 4480u * 4u;                      \
        uint32_t sB_ = sA_ + 2304u * 4u;                                        \
        _Pragma("unroll")                                                       \
        for (int h_ = 0; h_ < 2; ++h_) {                                        \
            int c_ = h_ * 256 + tid;                                            \
            int ar_ = c_ >> 3, kg_ = (c_ & 7) * 4;                              \
            int gk_ = kb_ + kg_;                                                \
            const float* ap_ = (gk_ < Asplit)                                   \
                ? (Ap0 + (size_t)(row0 + ar_) * lda + gk_)                      \
                : (Ap1 + (size_t)(row0 + ar_) * lda + (gk_ - Asplit));          \
            cpa16(sA_ + (uint32_t)(ar_ * 36 + kg_) * 4u, ap_);                  \
        }                                                                       \
        _Pragma("unroll")                                                       \
        for (int h_ = 0; h_ < 2; ++h_) {                                        \
            int c_ = h_ * 256 + tid;                                            \
            int br_ = c_ >> 4, cg_ = (c_ & 15) * 4;                             \
            cpa16(sB_ + (uint32_t)(br_ * 68 + cg_) * 4u,                        \
                  W + (size_t)(kb_ + br_) * N + col0 + cg_);                    \
        }                                                                       \
    } while (0)

    // prologue: tiles 0,1
    if (0 < nt) { GEMM_ISSUE(0, 0); } cpa_commit();
    if (1 < nt) { GEMM_ISSUE(1, 1); } cpa_commit();

    for (int ti = 0; ti < nt; ++ti) {
        cpa_wait<1>();
        __syncthreads();
        int tin = ti + 2;
        if (tin < nt) { GEMM_ISSUE(tin, tin % 3); }
        cpa_commit();

        const float* Ab = smg + (ti % 3) * 4480;
        const float* Bb = Ab + 2304;
        #pragma unroll
        for (int ks = 0; ks < 32; ks += 8) {
            int kk = ks + j;
            float a[2][4];
            #pragma unroll
            for (int mi = 0; mi < 2; ++mi) {
                int rr = wm + mi * 16 + g;
                a[mi][0] = Ab[rr * 36 + kk];       a[mi][1] = Ab[(rr + 8) * 36 + kk];
                a[mi][2] = Ab[rr * 36 + kk + 4];   a[mi][3] = Ab[(rr + 8) * 36 + kk + 4];
            }
            #pragma unroll
            for (int ni = 0; ni < 2; ++ni) {
                int nn = wn + ni * 8 + g;
                float b0 = f2tf(Bb[kk * 68 + nn]), b1 = f2tf(Bb[(kk + 4) * 68 + nn]);
                mma8(acc[0][ni], a[0][0], a[0][1], a[0][2], a[0][3], b0, b1);
                mma8(acc[1][ni], a[1][0], a[1][1], a[1][2], a[1][3], b0, b1);
            }
        }
        // no trailing __syncthreads — next top barrier orders stage reuse
    }
    #undef GEMM_ISSUE

    #pragma unroll
    for (int mi = 0; mi < 2; ++mi)
        #pragma unroll
        for (int ni = 0; ni < 2; ++ni) {
            int rr = row0 + wm + mi * 16 + g;
            int cc = col0 + wn + ni * 8 + 2 * j;
            float b0v = bias[cc], b1v = bias[cc + 1];
            float v0 = acc[mi][ni][0] + b0v, v1 = acc[mi][ni][1] + b1v;
            float v2 = acc[mi][ni][2] + b0v, v3 = acc[mi][ni][3] + b1v;
            if (doRelu) {
                v0 = fmaxf(v0, 0.f); v1 = fmaxf(v1, 0.f);
                v2 = fmaxf(v2, 0.f); v3 = fmaxf(v3, 0.f);
            }
            if (doRound) { v0 = f2tf(v0); v1 = f2tf(v1); v2 = f2tf(v2); v3 = f2tf(v3); }
            if (doPerm) {
                int c0p = dperm(cc), c1p = dperm(cc + 1);
                C[(size_t)rr * N + c0p] = v0; C[(size_t)rr * N + c1p] = v1;
                C[(size_t)(rr + 8) * N + c0p] = v2; C[(size_t)(rr + 8) * N + c1p] = v3;
            } else {
                *(float2*)(C + (size_t)rr * N + cc) = make_float2(v0, v1);
                *(float2*)(C + (size_t)(rr + 8) * N + cc) = make_float2(v2, v3);
            }
        }
}

// ---------- fused fc_fusion (both branches) + residual add -> d_out ----------
// A = g_O (pre-rounded); B = Wf raw, rounded in-loop.
// stage: A0[32*36]=1152, A1[32*36]=1152, B[32*68]=2176 -> 4480/stage x3
__global__ __launch_bounds__(256) void k_fuse(
    const float* __restrict__ audio, const float* __restrict__ video,
    const float* __restrict__ Wf, const float* __restrict__ bfb,
    float* __restrict__ out)
{
    extern __shared__ float smg[];
    uint32_t sb32 = (uint32_t)__cvta_generic_to_shared(smg);
    int tid = threadIdx.x, lane = tid & 31, warp = tid >> 5;
    int g = lane >> 2, j = lane & 3;
    int wm = (warp >> 2) * 16, wn = (warp & 3) * 16;
    int row0 = blockIdx.y * 32, col0 = blockIdx.x * 64;
    float acc[2][2][4] = {};   // [branch][ni][4]
    const int nt = 64;         // K = 2048

    #define FU_ISSUE(TI, ST) do {                                               \
        int kb_ = (TI) << 5;                                                    \
        uint32_t sA0_ = sb32 + (uint32_t)(ST) * 4480u * 4u;                     \
        uint32_t sA1_ = sA0_ + 1152u * 4u;                                      \
        uint32_t sB_  = sA1_ + 1152u * 4u;                                      \
        {                                                                       \
            int ar_ = tid >> 3, kg_ = (tid & 7) * 4;                            \
            cpa16(sA0_ + (uint32_t)(ar_ * 36 + kg_) * 4u,                       \
                  g_O + (size_t)(row0 + ar_) * 2048 + kb_ + kg_);               \
            cpa16(sA1_ + (uint32_t)(ar_ * 36 + kg_) * 4u,                       \
                  g_O + (size_t)(640 + row0 + ar_) * 2048 + kb_ + kg_);         \
        }                                                                       \
        _Pragma("unroll")                                                       \
        for (int h_ = 0; h_ < 2; ++h_) {                                        \
            int c_ = h_ * 256 + tid;                                            \
            int br_ = c_ >> 4, cg_ = (c_ & 15) * 4;                             \
            cpa16(sB_ + (uint32_t)(br_ * 68 + cg_) * 4u,                        \
                  Wf + (size_t)(kb_ + br_) * 1024 + col0 + cg_);                \
        }                                                                       \
    } while (0)

    FU_ISSUE(0, 0); cpa_commit();
    FU_ISSUE(1, 1); cpa_commit();

    for (int ti = 0; ti < nt; ++ti) {
        cpa_wait<1>();
        __syncthreads();
        int tin = ti + 2;
        if (tin < nt) { FU_ISSUE(tin, tin % 3); }
        cpa_commit();

        const float* S   = smg + (ti % 3) * 4480;
        const float* A0b = S;
        const float* A1b = S + 1152;
        const float* Bb  = S + 2304;
        #pragma unroll
        for (int ks = 0; ks < 32; ks += 8) {
            int kk = ks + j;
            int rr = wm + g;
            float a0[4], a1[4];
            a0[0] = A0b[rr * 36 + kk];     a0[1] = A0b[(rr + 8) * 36 + kk];
            a0[2] = A0b[rr * 36 + kk + 4]; a0[3] = A0b[(rr + 8) * 36 + kk + 4];
            a1[0] = A1b[rr * 36 + kk];     a1[1] = A1b[(rr + 8) * 36 + kk];
            a1[2] = A1b[rr * 36 + kk + 4]; a1[3] = A1b[(rr + 8) * 36 + kk + 4];
            #pragma unroll
            for (int ni = 0; ni < 2; ++ni) {
                int nn = wn + ni * 8 + g;
                float b0 = f2tf(Bb[kk * 68 + nn]), b1 = f2tf(Bb[(kk + 4) * 68 + nn]);
                mma8(acc[0][ni], a0[0], a0[1], a0[2], a0[3], b0, b1);
                mma8(acc[1][ni], a1[0], a1[1], a1[2], a1[3], b0, b1);
            }
        }
    }
    #undef FU_ISSUE

    #pragma unroll
    for (int ni = 0; ni < 2; ++ni) {
        int rr = row0 + wm + g, cc = col0 + wn + ni * 8 + 2 * j;
        float b0 = bfb[cc], b1 = bfb[cc + 1];
        size_t o0 = (size_t)rr * 1024 + cc, o1 = (size_t)(rr + 8) * 1024 + cc;
        float v0 = fmaxf(acc[0][ni][0] + b0, 0.f) + fmaxf(acc[1][ni][0] + b0, 0.f)
                 + audio[o0] + video[o0];
        float v1 = fmaxf(acc[0][ni][1] + b1, 0.f) + fmaxf(acc[1][ni][1] + b1, 0.f)
                 + audio[o0 + 1] + video[o0 + 1];
        float v2 = fmaxf(acc[0][ni][2] + b0, 0.f) + fmaxf(acc[1][ni][2] + b0, 0.f)
                 + audio[o1] + video[o1];
        float v3 = fmaxf(acc[0][ni][3] + b1, 0.f) + fmaxf(acc[1][ni][3] + b1, 0.f)
                 + audio[o1 + 1] + video[o1 + 1];
        *(float2*)(out + o0) = make_float2(v0, v1);
        *(float2*)(out + o1) = make_float2(v2, v3);
    }
}

// ---------- fused co-attention branch: 2 e-tiles/warp, cp.async 3-stage ----------
// stage layout (floats): K[64*20]=1280 then V[16*68]=1088 -> 2368/stage, 3 stages
__global__ __launch_bounds__(256, 3) void k_branch_tc()
{
    __shared__ float sm[3 * 2368];
    uint32_t sb32 = (uint32_t)__cvta_generic_to_shared(sm);

    int eblk = blockIdx.x, b = blockIdx.y, r = blockIdx.z;
    int tid = threadIdx.x, lane = tid & 31, warp = tid >> 5;
    int g = lane >> 2, j = lane & 3;

    const float* gk  = g_K + (size_t)(r * 64 + b) * 16384;
    const float* gvb = g_V + (size_t)r * 655360 + (size_t)b * 10240;

    // J fragments for both e-tiles (loop-invariant); g_J pre-rounded
    float jf[2][2][4];
    {
        const float* jb = g_J + (size_t)b * 20480;
        int e0 = eblk * 256 + warp * 32 + g;
        #pragma unroll
        for (int tile = 0; tile < 2; ++tile) {
            int eT = e0 + tile * 16;
            jf[tile][0][0] = jb[(size_t)j * 2048 + eT];
            jf[tile][0][1] = jb[(size_t)j * 2048 + eT + 8];
            jf[tile][0][2] = jb[(size_t)(j + 4) * 2048 + eT];
            jf[tile][0][3] = jb[(size_t)(j + 4) * 2048 + eT + 8];
            jf[tile][1][0] = (j < 2) ? jb[(size_t)(8 + j) * 2048 + eT] : 0.f;
            jf[tile][1][1] = (j < 2) ? jb[(size_t)(8 + j) * 2048 + eT + 8] : 0.f;
            jf[tile][1][2] = 0.f; jf[tile][1][3] = 0.f;
        }
    }

    // zero V pad rows (t=10..15) in all stages
    for (int i = tid; i < 3 * 6 * 68; i += 256) {
        int st = i / 408, rem = i - st * 408;
        sm[st * 2368 + 1280 + (10 + rem / 68) * 68 + (rem % 68)] = 0.0f;
    }

    #define BR_ISSUE(CH, ST) do {                                               \
        uint32_t kb_ = sb32 + (uint32_t)(ST) * 2368u * 4u;                      \
        int d_ = tid >> 2, k4_ = (tid & 3) * 4;                                 \
        cpa16(kb_ + (uint32_t)(d_ * 20 + k4_) * 4u,                             \
              gk + (size_t)((CH) * 64 + d_) * 16 + k4_);                        \
        if (tid < 160) {                                                        \
            int t_ = tid >> 4, d4_ = (tid & 15) * 4;                            \
            cpa16(kb_ + (uint32_t)(1280 + t_ * 68 + d4_) * 4u,                  \
                  gvb + (size_t)t_ * 1024 + (CH) * 64 + d4_);                   \
        }                                                                       \
    } while (0)

    BR_ISSUE(0, 0); cpa_commit();
    BR_ISSUE(1, 1); cpa_commit();

    float accW[2][2][4] = {};

    for (int ch = 0; ch < 16; ++ch) {
        cpa_wait<1>();
        __syncthreads();
        if (ch + 2 < 16) { BR_ISSUE(ch + 2, (ch + 2) % 3); }
        cpa_commit();

        const float* Kb = sm + (ch % 3) * 2368;
        const float* Vb = Kb + 1280;

        #pragma unroll
        for (int dh = 0; dh < 2; ++dh) {
            float accS[2][4][4] = {};
            #pragma unroll
            for (int s = 0; s < 2; ++s) {
                int kk = s * 8 + j;
                #pragma unroll
                for (int ni = 0; ni < 4; ++ni) {
                    int dd = dh * 32 + ni * 8 + g;
                    float b0 = Kb[dd * 20 + kk], b1 = Kb[dd * 20 + kk + 4];
                    mma8(accS[0][ni], jf[0][s][0], jf[0][s][1], jf[0][s][2], jf[0][s][3], b0, b1);
                    mma8(accS[1][ni], jf[1][s][0], jf[1][s][1], jf[1][s][2], jf[1][s][3], b0, b1);
                }
            }
            #pragma unroll
            for (int ni = 0; ni < 4; ++ni) {
                float a0A = f2tf(tanhx(accS[0][ni][0]));
                float a1A = f2tf(tanhx(accS[0][ni][2]));
                float a2A = f2tf(tanhx(accS[0][ni][1]));
                float a3A = f2tf(tanhx(accS[0][ni][3]));
                float a0B = f2tf(tanhx(accS[1][ni][0]));
                float a1B = f2tf(tanhx(accS[1][ni][2]));
                float a2B = f2tf(tanhx(accS[1][ni][1]));
                float a3B = f2tf(tanhx(accS[1][ni][3]));
                #pragma unroll
                for (int nt = 0; nt < 2; ++nt) {
                    float2 bv = *(const float2*)&Vb[(nt * 8 + g) * 68 + dh * 32 + ni * 8 + 2 * j];
                    mma8(accW[0][nt], a0A, a1A, a2A, a3A, bv.x, bv.y);
                    mma8(accW[1][nt], a0B, a1B, a2B, a3B, bv.x, bv.y);
                }
            }
        }
    }
    #undef BR_ISSUE

    // epilogue: g_O = tf32(relu(tanh(accW)))
    #pragma unroll
    for (int tile = 0; tile < 2; ++tile) {
        int e = eblk * 256 + warp * 32 + tile * 16 + g;
        #pragma unroll
        for (int nt = 0; nt < 2; ++nt) {
            #pragma unroll
            for (int jj = 0; jj < 2; ++jj) {
                int t = nt * 8 + 2 * j + jj;
                if (t < 10) {
                    size_t rowoff = ((size_t)r * 640 + b * 10 + t) * 2048;
                    g_O[rowoff + e]     = f2tf(fmaxf(tanhx(accW[tile][nt][jj]), 0.0f));
                    g_O[rowoff + e + 8] = f2tf(fmaxf(tanhx(accW[tile][nt][2 + jj]), 0.0f));
                }
            }
        }
    }
}

extern "C" void kernel_launch(void* const* d_in, const int* in_sizes, int n_in,
                              void* d_out, int out_size)
{
    const float* audio = (const float*)d_in[0];
    const float* video = (const float*)d_in[1];
    const float* Wq  = (const float*)d_in[2];
    const float* bq  = (const float*)d_in[3];
    const float* Wk1 = (const float*)d_in[4];
    const float* bk1 = (const float*)d_in[5];
    const float* Wk2 = (const float*)d_in[6];
    const float* bk2 = (const float*)d_in[7];
    const float* Wv1 = (const float*)d_in[8];
    const float* bv1 = (const float*)d_in[9];
    const float* Wv2 = (const float*)d_in[10];
    const float* bv2 = (const float*)d_in[11];
    const float* Wf  = (const float*)d_in[12];
    const float* bf  = (const float*)d_in[13];
    float* out = (float*)d_out;

    static float* wb = nullptr;
    static cudaStream_t s1 = nullptr, s2 = nullptr;
    static cudaEvent_t eS, eR, eK, eV;
    if (!wb) {
        cudaGetSymbolAddress((void**)&wb, g_W);
        cudaFuncSetAttribute(k_gemm_tc, cudaFuncAttributeMaxDynamicSharedMemorySize, 53760);
        cudaFuncSetAttribute(k_fuse,    cudaFuncAttributeMaxDynamicSharedMemorySize, 53760);
        cudaStreamCreateWithFlags(&s1, cudaStreamNonBlocking);
        cudaStreamCreateWithFlags(&s2, cudaStreamNonBlocking);
        cudaEventCreateWithFlags(&eS, cudaEventDisableTiming);
        cudaEventCreateWithFlags(&eR, cudaEventDisableTiming);
        cudaEventCreateWithFlags(&eK, cudaEventDisableTiming);
        cudaEventCreateWithFlags(&eV, cudaEventDisableTiming);
    }

    // fork: key linears on s2 (uses raw inputs)
    cudaEventRecord(eS, 0);
    cudaStreamWaitEvent(s2, eS, 0);
    k_key<<<dim3(64, 2), 256, 0, s2>>>(audio, video, Wk1, bk1, Wk2, bk2);
    cudaEventRecord(eK, s2);

    // pre-round activations only (weights rounded in-loop in the GEMMs)
    k_round_av<<<1280, 256>>>(audio, video);
    cudaEventRecord(eR, 0);

    // val1/val2 on s1, concurrent with joint on main stream
    cudaStreamWaitEvent(s1, eR, 0);
    k_gemm_tc<<<dim3(16, 10, 2), 256, 53760, s1>>>(
        wb + OW_A, wb + OW_A, wb + OW_V, wb + OW_V, -1, 1024, 1024,
        Wv1, Wv2, bv1, bv2, 1, (size_t)640 * 1024,
        640, 1024, 1024, 0, 1, 1);
    cudaEventRecord(eV, s1);

    // joint = concat(audio,video) @ Wq + bq  [640x2048] K=2048 -> g_J (rounded)
    k_gemm_tc<<<dim3(32, 10), 256, 53760>>>(
        wb + OW_A, wb + OW_V, wb + OW_A, wb + OW_V, -1, 1024, 1024,
        Wq, Wq, bq, bq, 0, 0, 640, 2048, 2048, 0, 1, 0);

    // join: branch needs joint + val + key
    cudaStreamWaitEvent(0, eV, 0);
    cudaStreamWaitEvent(0, eK, 0);
    k_branch_tc<<<dim3(8, 64, 2), 256>>>();

    // fused fc_fusion (both branches) + residual -> d_out
    k_fuse<<<dim3(16, 20), 256, 53760>>>(audio, video, Wf, bf, out);
}

// round 13
// speedup vs baseline: 1.5758x; 1.5758x over previous
#include <cuda_runtime.h>
#include <cuda_fp16.h>
#include <cstdint>

#define DINL __device__ __forceinline__
#define SCALE_F 0.022097086912079608f  // 1/sqrt(2048)

// ---------- scratch (all fp16) ----------
__device__ __half g_J[640 * 2048];           // joint [b*10+t][e]
__device__ __half g_K[2 * 64 * 1024 * 16];   // keys, SCALE folded, [r][b][d][t16]
__device__ __half g_V[2 * 640 * 1024];       // values [r][row][d]
__device__ __half g_O[2 * 640 * 2048];       // relu(tanh(weighted)) [r*640+row][e]
__device__ __half g_W[9699328];              // converted: [audio|video|Wq|Wv1|Wv2|Wf]
// weights stored k-pair interleaved: u32[r*N+n] = half2(W[2r][n], W[2r+1][n])

#define OW_A   0
#define OW_V   655360
#define OW_WQ  1310720
#define OW_WV1 5505024
#define OW_WV2 6553600
#define OW_WF  7602176

DINL float tanhx(float x) {
    float y; asm("tanh.approx.f32 %0, %1;" : "=f"(y) : "f"(x)); return y;
}
DINL uint32_t h2u(float lo, float hi) {  // pack two f32 -> f16x2 (lo in low bits)
    uint32_t r; asm("cvt.rn.f16x2.f32 %0, %1, %2;" : "=r"(r) : "f"(hi), "f"(lo));
    return r;
}
DINL uint32_t hh2u(__half lo, __half hi) {
    __half2 h = __halves2half2(lo, hi);
    return *reinterpret_cast<uint32_t*>(&h);
}
DINL void mma16(float* c, uint32_t a0, uint32_t a1, uint32_t a2, uint32_t a3,
                uint32_t b0, uint32_t b1) {
    asm volatile(
        "mma.sync.aligned.m16n8k16.row.col.f32.f16.f16.f32 "
        "{%0,%1,%2,%3},{%4,%5,%6,%7},{%8,%9},{%0,%1,%2,%3};"
        : "+f"(c[0]), "+f"(c[1]), "+f"(c[2]), "+f"(c[3])
        : "r"(a0), "r"(a1), "r"(a2), "r"(a3), "r"(b0), "r"(b1));
}
DINL void cpa16(uint32_t dst, const void* src) {
    asm volatile("cp.async.cg.shared.global [%0], [%1], 16;\n" :: "r"(dst), "l"(src));
}
DINL void cpa_commit() { asm volatile("cp.async.commit_group;\n" ::: "memory"); }
template<int W> DINL void cpa_wait() {
    asm volatile("cp.async.wait_group %0;\n" :: "n"(W) : "memory");
}

// ---------- convert inputs + weights to fp16 (weights: k-pair interleaved) ----------
__global__ __launch_bounds__(256) void k_round(
    const float* __restrict__ a, const float* __restrict__ v,
    const float* __restrict__ wq, const float* __restrict__ wv1,
    const float* __restrict__ wv2, const float* __restrict__ wf)
{
    int i = blockIdx.x * 256 + threadIdx.x;     // 16B output chunk (8 halves)
    uint4 o;
    if (i < 163840) {                            // activations, natural layout
        const float4* src = (i < 81920) ? (const float4*)a : (const float4*)v;
        int b4 = (i < 81920) ? 0 : 81920;
        float4 x0 = src[(size_t)(i - b4) * 2], x1 = src[(size_t)(i - b4) * 2 + 1];
        o.x = h2u(x0.x, x0.y); o.y = h2u(x0.z, x0.w);
        o.z = h2u(x1.x, x1.y); o.w = h2u(x1.z, x1.w);
    } else {                                     // weights, interleaved k-pairs
        const float* W; int N, cb;
        if      (i < 688128) { W = wq;  N = 2048; cb = 163840; }
        else if (i < 819200) { W = wv1; N = 1024; cb = 688128; }
        else if (i < 950272) { W = wv2; N = 1024; cb = 819200; }
        else                 { W = wf;  N = 1024; cb = 950272; }
        int u = (i - cb) * 4;
        int r = u / N, n = u - r * N;
        float4 w0 = *(const float4*)(W + (size_t)(2 * r) * N + n);
        float4 w1 = *(const float4*)(W + (size_t)(2 * r + 1) * N + n);
        o.x = h2u(w0.x, w1.x); o.y = h2u(w0.y, w1.y);
        o.z = h2u(w0.z, w1.z); o.w = h2u(w0.w, w1.w);
    }
    ((uint4*)g_W)[i] = o;
}

// ---------- key linears ----------
__global__ __launch_bounds__(256) void k_key(
    const float* __restrict__ audio, const float* __restrict__ video,
    const float* __restrict__ Wk1, const float* __restrict__ bk1,
    const float* __restrict__ Wk2, const float* __restrict__ bk2)
{
    int b = blockIdx.x, r = blockIdx.y;
    const float* X  = r ? video : audio;
    const float* Wk = r ? Wk2 : Wk1;
    const float* bk = r ? bk2 : bk1;
    __shared__ float sW[100], sb[10];
    if (threadIdx.x < 100) sW[threadIdx.x] = Wk[threadIdx.x];
    if (threadIdx.x < 10)  sb[threadIdx.x] = bk[threadIdx.x];
    __syncthreads();
    const float* xb = X + (size_t)b * 10240;
    __half* kout = g_K + (size_t)(r * 64 + b) * 16384;
    for (int d = threadIdx.x; d < 1024; d += 256) {
        float a[10];
        #pragma unroll
        for (int t = 0; t < 10; ++t) a[t] = xb[t * 1024 + d];
        __half* krow = kout + (size_t)d * 16;
        #pragma unroll
        for (int t = 10; t < 16; ++t) krow[t] = __float2half(0.0f);
        #pragma unroll
        for (int t = 0; t < 10; ++t) {
            float s = sb[t];
            #pragma unroll
            for (int tp = 0; tp < 10; ++tp) s += a[tp] * sW[tp * 10 + t];
            krow[t] = __float2half_rn(s * SCALE_F);
        }
    }
}

// ---------- fp16 GEMM: BM=64 BN=64 BK=32, 3-stage cp.async ----------
// stage bytes: A[64][40]h = 5120, B[16][72]u32 = 4608 -> 9728/stage
__global__ __launch_bounds__(256) void k_gemm_tc(
    const __half* A0, const __half* A1, const __half* A0z, const __half* A1z,
    int Asplit, int lda,
    const uint32_t* W0, const uint32_t* W1,
    const float* bias0, const float* bias1,
    int cSel, size_t cStride, int N, int K)
{
    extern __shared__ float smg[];
    char* smb = (char*)smg;
    uint32_t sb32 = (uint32_t)__cvta_generic_to_shared(smg);
    int z = blockIdx.z;
    const __half* Ap0 = z ? A0z : A0;
    const __half* Ap1 = z ? A1z : A1;
    const uint32_t* W  = z ? W1 : W0;
    const float* bias  = z ? bias1 : bias0;
    __half* C = (cSel == 0 ? g_J : g_V) + (size_t)z * cStride;

    int tid = threadIdx.x, lane = tid & 31, warp = tid >> 5;
    int g = lane >> 2, j = lane & 3;
    int wm = (warp >> 2) * 32, wn = (warp & 3) * 16;
    int row0 = blockIdx.y * 64, col0 = blockIdx.x * 64;
    float acc[2][2][4] = {};
    int nt = K >> 5;

    #define GEMM_ISSUE(TI, ST) do {                                             \
        int kb_ = (TI) << 5;                                                    \
        uint32_t sA_ = sb32 + (uint32_t)(ST) * 9728u;                           \
        uint32_t sB_ = sA_ + 5120u;                                             \
        { int ar_ = tid >> 2, g4_ = tid & 3;                                    \
          int gk_ = kb_ + g4_ * 8;                                              \
          const __half* ap_ = (gk_ < Asplit)                                    \
              ? (Ap0 + (size_t)(row0 + ar_) * lda + gk_)                        \
              : (Ap1 + (size_t)(row0 + ar_) * lda + (gk_ - Asplit));            \
          cpa16(sA_ + (uint32_t)(ar_ * 80 + g4_ * 16), ap_); }                  \
        { int br_ = tid >> 4, g4_ = tid & 15;                                   \
          cpa16(sB_ + (uint32_t)(br_ * 288 + g4_ * 16),                         \
                W + (size_t)((TI) * 16 + br_) * N + col0 + g4_ * 4); }          \
    } while (0)

    if (0 < nt) { GEMM_ISSUE(0, 0); } cpa_commit();
    if (1 < nt) { GEMM_ISSUE(1, 1); } cpa_commit();

    for (int ti = 0; ti < nt; ++ti) {
        cpa_wait<1>();
        __syncthreads();
        int tin = ti + 2;
        if (tin < nt) { GEMM_ISSUE(tin, tin % 3); }
        cpa_commit();

        const uint32_t* Asu = (const uint32_t*)(smb + (ti % 3) * 9728);
        const uint32_t* Bsu = (const uint32_t*)(smb + (ti % 3) * 9728 + 5120);
        #pragma unroll
        for (int s = 0; s < 2; ++s) {
            uint32_t a[2][4];
            #pragma unroll
            for (int mi = 0; mi < 2; ++mi) {
                int rr = wm + mi * 16 + g;
                a[mi][0] = Asu[rr * 20 + s * 8 + j];
                a[mi][1] = Asu[(rr + 8) * 20 + s * 8 + j];
                a[mi][2] = Asu[rr * 20 + s * 8 + 4 + j];
                a[mi][3] = Asu[(rr + 8) * 20 + s * 8 + 4 + j];
            }
            #pragma unroll
            for (int ni = 0; ni < 2; ++ni) {
                int nn = wn + ni * 8 + g;
                uint32_t b0 = Bsu[(s * 8 + j) * 72 + nn];
                uint32_t b1 = Bsu[(s * 8 + 4 + j) * 72 + nn];
                mma16(acc[0][ni], a[0][0], a[0][1], a[0][2], a[0][3], b0, b1);
                mma16(acc[1][ni], a[1][0], a[1][1], a[1][2], a[1][3], b0, b1);
            }
        }
    }
    #undef GEMM_ISSUE

    #pragma unroll
    for (int mi = 0; mi < 2; ++mi)
        #pragma unroll
        for (int ni = 0; ni < 2; ++ni) {
            int rr = row0 + wm + mi * 16 + g;
            int cc = col0 + wn + ni * 8 + 2 * j;
            float b0v = bias[cc], b1v = bias[cc + 1];
            float v0 = acc[mi][ni][0] + b0v, v1 = acc[mi][ni][1] + b1v;
            float v2 = acc[mi][ni][2] + b0v, v3 = acc[mi][ni][3] + b1v;
            *(uint32_t*)(C + (size_t)rr * N + cc) = h2u(v0, v1);
            *(uint32_t*)(C + (size_t)(rr + 8) * N + cc) = h2u(v2, v3);
        }
}

// ---------- fused fc_fusion (both branches) + residual -> d_out ----------
// stage: A0[32][40]h=2560, A1=2560, B[16][72]u32=4608 -> 9728/stage
__global__ __launch_bounds__(256) void k_fuse(
    const float* __restrict__ audio, const float* __restrict__ video,
    const uint32_t* __restrict__ Wfu, const float* __restrict__ bfb,
    float* __restrict__ out)
{
    extern __shared__ float smg[];
    char* smb = (char*)smg;
    uint32_t sb32 = (uint32_t)__cvta_generic_to_shared(smg);
    int tid = threadIdx.x, lane = tid & 31, warp = tid >> 5;
    int g = lane >> 2, j = lane & 3;
    int wm = (warp >> 2) * 16, wn = (warp & 3) * 16;
    int row0 = blockIdx.y * 32, col0 = blockIdx.x * 64;
    float acc[2][2][4] = {};
    const int nt = 64;   // K = 2048

    #define FU_ISSUE(TI, ST) do {                                               \
        int kb_ = (TI) << 5;                                                    \
        uint32_t sA0_ = sb32 + (uint32_t)(ST) * 9728u;                          \
        uint32_t sB_  = sA0_ + 5120u;                                           \
        if (tid < 128) {                                                        \
            int r_ = tid >> 2, g4_ = tid & 3;                                   \
            cpa16(sA0_ + (uint32_t)(r_ * 80 + g4_ * 16),                        \
                  g_O + (size_t)(row0 + r_) * 2048 + kb_ + g4_ * 8);            \
        } else {                                                                \
            int t2 = tid - 128, r_ = t2 >> 2, g4_ = t2 & 3;                     \
            cpa16(sA0_ + 2560u + (uint32_t)(r_ * 80 + g4_ * 16),                \
                  g_O + (size_t)(640 + row0 + r_) * 2048 + kb_ + g4_ * 8);      \
        }                                                                       \
        { int br_ = tid >> 4, g4_ = tid & 15;                                   \
          cpa16(sB_ + (uint32_t)(br_ * 288 + g4_ * 16),                         \
                Wfu + (size_t)((TI) * 16 + br_) * 1024 + col0 + g4_ * 4); }     \
    } while (0)

    FU_ISSUE(0, 0); cpa_commit();
    FU_ISSUE(1, 1); cpa_commit();

    for (int ti = 0; ti < nt; ++ti) {
        cpa_wait<1>();
        __syncthreads();
        int tin = ti + 2;
        if (tin < nt) { FU_ISSUE(tin, tin % 3); }
        cpa_commit();

        const uint32_t* A0u = (const uint32_t*)(smb + (ti % 3) * 9728);
        const uint32_t* A1u = A0u + 640;
        const uint32_t* Bsu = (const uint32_t*)(smb + (ti % 3) * 9728 + 5120);
        #pragma unroll
        for (int s = 0; s < 2; ++s) {
            int rr = wm + g;
            uint32_t a0[4], a1[4];
            a0[0] = A0u[rr * 20 + s * 8 + j];       a0[1] = A0u[(rr + 8) * 20 + s * 8 + j];
            a0[2] = A0u[rr * 20 + s * 8 + 4 + j];   a0[3] = A0u[(rr + 8) * 20 + s * 8 + 4 + j];
            a1[0] = A1u[rr * 20 + s * 8 + j];       a1[1] = A1u[(rr + 8) * 20 + s * 8 + j];
            a1[2] = A1u[rr * 20 + s * 8 + 4 + j];   a1[3] = A1u[(rr + 8) * 20 + s * 8 + 4 + j];
            #pragma unroll
            for (int ni = 0; ni < 2; ++ni) {
                int nn = wn + ni * 8 + g;
                uint32_t b0 = Bsu[(s * 8 + j) * 72 + nn];
                uint32_t b1 = Bsu[(s * 8 + 4 + j) * 72 + nn];
                mma16(acc[0][ni], a0[0], a0[1], a0[2], a0[3], b0, b1);
                mma16(acc[1][ni], a1[0], a1[1], a1[2], a1[3], b0, b1);
            }
        }
    }
    #undef FU_ISSUE

    #pragma unroll
    for (int ni = 0; ni < 2; ++ni) {
        int rr = row0 + wm + g, cc = col0 + wn + ni * 8 + 2 * j;
        float b0 = bfb[cc], b1 = bfb[cc + 1];
        size_t o0 = (size_t)rr * 1024 + cc, o1 = (size_t)(rr + 8) * 1024 + cc;
        float v0 = fmaxf(acc[0][ni][0] + b0, 0.f) + fmaxf(acc[1][ni][0] + b0, 0.f)
                 + audio[o0] + video[o0];
        float v1 = fmaxf(acc[0][ni][1] + b1, 0.f) + fmaxf(acc[1][ni][1] + b1, 0.f)
                 + audio[o0 + 1] + video[o0 + 1];
        float v2 = fmaxf(acc[0][ni][2] + b0, 0.f) + fmaxf(acc[1][ni][2] + b0, 0.f)
                 + audio[o1] + video[o1];
        float v3 = fmaxf(acc[0][ni][3] + b1, 0.f) + fmaxf(acc[1][ni][3] + b1, 0.f)
                 + audio[o1 + 1] + video[o1 + 1];
        *(float2*)(out + o0) = make_float2(v0, v1);
        *(float2*)(out + o1) = make_float2(v2, v3);
    }
}

// ---------- fused co-attention branch, fp16: 2 e-tiles/warp, 3-stage ----------
// stage bytes: K[64][24]h = 3072, V[16][72]h = 2304 -> 5376/stage
__global__ __launch_bounds__(256, 2) void k_branch_tc()
{
    __shared__ char smb[3 * 5376];
    uint32_t sb32 = (uint32_t)__cvta_generic_to_shared(smb);

    int eblk = blockIdx.x, b = blockIdx.y, r = blockIdx.z;
    int tid = threadIdx.x, lane = tid & 31, warp = tid >> 5;
    int g = lane >> 2, j = lane & 3;

    const __half* gk  = g_K + (size_t)(r * 64 + b) * 16384;
    const __half* gvb = g_V + (size_t)r * 655360 + (size_t)b * 10240;

    // J fragments (A of GEMM1, k=t covers all 16 padded t in ONE mma)
    uint32_t jf[2][4];
    {
        const __half* jb = g_J + (size_t)b * 20480;
        __half z16 = __float2half(0.0f);
        #pragma unroll
        for (int tile = 0; tile < 2; ++tile) {
            int eT = eblk * 256 + warp * 32 + tile * 16 + g;
            jf[tile][0] = hh2u(jb[(size_t)(2 * j) * 2048 + eT],
                               jb[(size_t)(2 * j + 1) * 2048 + eT]);
            jf[tile][1] = hh2u(jb[(size_t)(2 * j) * 2048 + eT + 8],
                               jb[(size_t)(2 * j + 1) * 2048 + eT + 8]);
            if (j == 0) {
                jf[tile][2] = hh2u(jb[(size_t)8 * 2048 + eT], jb[(size_t)9 * 2048 + eT]);
                jf[tile][3] = hh2u(jb[(size_t)8 * 2048 + eT + 8], jb[(size_t)9 * 2048 + eT + 8]);
            } else { jf[tile][2] = 0u; jf[tile][3] = 0u; }
            (void)z16;
        }
    }

    // zero V pad rows (t=10..15) in all 3 stages
    for (int i = tid; i < 3 * 6 * 36; i += 256) {
        int st = i / 216, rem = i - st * 216;
        int row = 10 + rem / 36, col = rem % 36;
        ((uint32_t*)(smb + st * 5376 + 3072))[row * 36 + col] = 0u;
    }

    #define BR_ISSUE(CH, ST) do {                                               \
        uint32_t base_ = sb32 + (uint32_t)(ST) * 5376u;                         \
        if (tid < 128) {                                                        \
            int d_ = tid >> 1, g4_ = tid & 1;                                   \
            cpa16(base_ + (uint32_t)(d_ * 48 + g4_ * 16),                       \
                  gk + (size_t)((CH) * 64 + d_) * 16 + g4_ * 8);                \
        } else if (tid < 208) {                                                 \
            int v_ = tid - 128, t_ = v_ >> 3, gi_ = v_ & 7;                     \
            cpa16(base_ + 3072u + (uint32_t)(t_ * 144 + gi_ * 16),              \
                  gvb + (size_t)t_ * 1024 + (CH) * 64 + gi_ * 8);               \
        }                                                                       \
    } while (0)

    BR_ISSUE(0, 0); cpa_commit();
    BR_ISSUE(1, 1); cpa_commit();

    float accW[2][2][4] = {};

    for (int ch = 0; ch < 16; ++ch) {
        cpa_wait<1>();
        __syncthreads();
        if (ch + 2 < 16) { BR_ISSUE(ch + 2, (ch + 2) % 3); }
        cpa_commit();

        const uint32_t* Ku = (const uint32_t*)(smb + (ch % 3) * 5376);        // stride 12
        const uint32_t* Vu = (const uint32_t*)(smb + (ch % 3) * 5376 + 3072); // stride 36

        #pragma unroll
        for (int dh = 0; dh < 2; ++dh) {
            float accS[2][4][4] = {};
            // GEMM1: S^T[e,d] += J^T K^T over k=t(16), one mma per (e-tile, d8)
            #pragma unroll
            for (int ni = 0; ni < 4; ++ni) {
                int dd = dh * 32 + ni * 8 + g;
                uint32_t b0 = Ku[dd * 12 + j];
                uint32_t b1 = Ku[dd * 12 + 4 + j];
                mma16(accS[0][ni], jf[0][0], jf[0][1], jf[0][2], jf[0][3], b0, b1);
                mma16(accS[1][ni], jf[1][0], jf[1][1], jf[1][2], jf[1][3], b0, b1);
            }
            // tanh -> fp16 A fragments (C->A identity), GEMM2 over k=d(16) chunks
            #pragma unroll
            for (int q = 0; q < 2; ++q) {
                uint32_t aa[2][4];
                #pragma unroll
                for (int et = 0; et < 2; ++et) {
                    aa[et][0] = h2u(tanhx(accS[et][2 * q][0]),     tanhx(accS[et][2 * q][1]));
                    aa[et][1] = h2u(tanhx(accS[et][2 * q][2]),     tanhx(accS[et][2 * q][3]));
                    aa[et][2] = h2u(tanhx(accS[et][2 * q + 1][0]), tanhx(accS[et][2 * q + 1][1]));
                    aa[et][3] = h2u(tanhx(accS[et][2 * q + 1][2]), tanhx(accS[et][2 * q + 1][3]));
                }
                #pragma unroll
                for (int nt = 0; nt < 2; ++nt) {
                    int tt = nt * 8 + g;
                    uint32_t b0 = Vu[tt * 36 + dh * 16 + q * 8 + j];
                    uint32_t b1 = Vu[tt * 36 + dh * 16 + q * 8 + 4 + j];
                    mma16(accW[0][nt], aa[0][0], aa[0][1], aa[0][2], aa[0][3], b0, b1);
                    mma16(accW[1][nt], aa[1][0], aa[1][1], aa[1][2], aa[1][3], b0, b1);
                }
            }
        }
    }
    #undef BR_ISSUE

    // epilogue: g_O[t][e] = fp16(relu(tanh(accW)))
    #pragma unroll
    for (int et = 0; et < 2; ++et) {
        int e = eblk * 256 + warp * 32 + et * 16 + g;
        #pragma unroll
        for (int nt = 0; nt < 2; ++nt) {
            int t0 = nt * 8 + 2 * j;
            if (t0 < 10) {
                size_t base = ((size_t)r * 640 + b * 10 + t0) * 2048;
                g_O[base + e]     = __float2half_rn(fmaxf(tanhx(accW[et][nt][0]), 0.0f));
                g_O[base + e + 8] = __float2half_rn(fmaxf(tanhx(accW[et][nt][2]), 0.0f));
            }
            if (t0 + 1 < 10) {
                size_t base = ((size_t)r * 640 + b * 10 + t0 + 1) * 2048;
                g_O[base + e]     = __float2half_rn(fmaxf(tanhx(accW[et][nt][1]), 0.0f));
                g_O[base + e + 8] = __float2half_rn(fmaxf(tanhx(accW[et][nt][3]), 0.0f));
            }
        }
    }
}

extern "C" void kernel_launch(void* const* d_in, const int* in_sizes, int n_in,
                              void* d_out, int out_size)
{
    const float* audio = (const float*)d_in[0];
    const float* video = (const float*)d_in[1];
    const float* Wq  = (const float*)d_in[2];
    const float* bq  = (const float*)d_in[3];
    const float* Wk1 = (const float*)d_in[4];
    const float* bk1 = (const float*)d_in[5];
    const float* Wk2 = (const float*)d_in[6];
    const float* bk2 = (const float*)d_in[7];
    const float* Wv1 = (const float*)d_in[8];
    const float* bv1 = (const float*)d_in[9];
    const float* Wv2 = (const float*)d_in[10];
    const float* bv2 = (const float*)d_in[11];
    const float* Wf  = (const float*)d_in[12];
    const float* bf  = (const float*)d_in[13];
    float* out = (float*)d_out;

    static __half* wb = nullptr;
    static cudaStream_t s1 = nullptr, s2 = nullptr;
    static cudaEvent_t eS, eR, eK, eV;
    if (!wb) {
        cudaGetSymbolAddress((void**)&wb, g_W);
        cudaStreamCreateWithFlags(&s1, cudaStreamNonBlocking);
        cudaStreamCreateWithFlags(&s2, cudaStreamNonBlocking);
        cudaEventCreateWithFlags(&eS, cudaEventDisableTiming);
        cudaEventCreateWithFlags(&eR, cudaEventDisableTiming);
        cudaEventCreateWithFlags(&eK, cudaEventDisableTiming);
        cudaEventCreateWithFlags(&eV, cudaEventDisableTiming);
    }
    const __half* hA = wb + OW_A;
    const __half* hV = wb + OW_V;
    const uint32_t* Wqu  = (const uint32_t*)(wb + OW_WQ);
    const uint32_t* Wv1u = (const uint32_t*)(wb + OW_WV1);
    const uint32_t* Wv2u = (const uint32_t*)(wb + OW_WV2);
    const uint32_t* Wfu  = (const uint32_t*)(wb + OW_WF);

    // fork: key linears on s2 (raw fp32 inputs)
    cudaEventRecord(eS, 0);
    cudaStreamWaitEvent(s2, eS, 0);
    k_key<<<dim3(64, 2), 256, 0, s2>>>(audio, video, Wk1, bk1, Wk2, bk2);
    cudaEventRecord(eK, s2);

    // fp16 conversion (activations natural, weights k-pair interleaved)
    k_round<<<4736, 256>>>(audio, video, Wq, Wv1, Wv2, Wf);
    cudaEventRecord(eR, 0);

    // val1/val2 on s1 (z), concurrent with joint
    cudaStreamWaitEvent(s1, eR, 0);
    k_gemm_tc<<<dim3(16, 10, 2), 256, 29184, s1>>>(
        hA, hA, hV, hV, 1024, 1024, Wv1u, Wv2u, bv1, bv2,
        1, (size_t)640 * 1024, 1024, 1024);
    cudaEventRecord(eV, s1);

    // joint = concat(audio,video) @ Wq + bq -> g_J
    k_gemm_tc<<<dim3(32, 10), 256, 29184>>>(
        hA, hV, hA, hV, 1024, 1024, Wqu, Wqu, bq, bq,
        0, 0, 2048, 2048);

    // join, then branch
    cudaStreamWaitEvent(0, eV, 0);
    cudaStreamWaitEvent(0, eK, 0);
    k_branch_tc<<<dim3(8, 64, 2), 256>>>();

    // fused fc_fusion (both branches) + residual -> d_out
    k_fuse<<<dim3(16, 20), 256, 29184>>>(audio, video, Wfu, bf, out);
}